// round 14
// baseline (speedup 1.0000x reference)
#include <cuda_runtime.h>
#include <math.h>

// Problem dims
#define BB   2
#define LTT  2048
#define LSS  2048
#define DD   1024
#define HH   16
#define DKK  64
#define DFFF 4096
#define MR   (BB*LTT)   // 4096 rows
#define BH   (BB*HH)    // 32

// ---------------- scratch (__device__ globals, no allocs) ----------------
__device__ float g_q   [(size_t)MR*DD];
__device__ float g_k   [(size_t)MR*DD];
__device__ float g_v   [(size_t)MR*DD];
__device__ float g_attn[(size_t)MR*DD];
__device__ float g_tmp [(size_t)MR*DD];
__device__ float g_x1  [(size_t)MR*DD];
__device__ float g_x2  [(size_t)MR*DD];
__device__ float g_ff  [(size_t)MR*DFFF];

// ------------------------- tf32 helpers -----------------------------------
__device__ __forceinline__ unsigned f2tf32(float x) {
    unsigned y;
    asm("cvt.rna.tf32.f32 %0, %1;" : "=r"(y) : "f"(x));
    return y;
}
__device__ __forceinline__ unsigned raw2tf32(unsigned r) {
    return f2tf32(__uint_as_float(r));
}

// D += A(16x8) @ B(8x8), tf32 in, fp32 accum.  row.col layout.
__device__ __forceinline__ void mma8(float* d, const unsigned* a, const unsigned* b) {
    asm volatile(
        "mma.sync.aligned.m16n8k8.row.col.f32.tf32.tf32.f32 "
        "{%0,%1,%2,%3},{%4,%5,%6,%7},{%8,%9},{%0,%1,%2,%3};\n"
        : "+f"(d[0]), "+f"(d[1]), "+f"(d[2]), "+f"(d[3])
        : "r"(a[0]), "r"(a[1]), "r"(a[2]), "r"(a[3]), "r"(b[0]), "r"(b[1]));
}

// 16B async copy gmem -> smem
__device__ __forceinline__ void cpa16(unsigned* dst, const void* src) {
    unsigned d = (unsigned)__cvta_generic_to_shared(dst);
    asm volatile("cp.async.cg.shared.global [%0], [%1], 16;\n" :: "r"(d), "l"(src));
}

// ---------------- TF32 GEMM: C = A[M,K] @ W[K,N] + bias (+gelu) -----------
// CTA = 128 threads (4 warps), tile 64x128, BK=32, warp tile 64x32.
// 4 CTAs/SM -> 4 independent barrier domains (vs 2 at 256-thr CTAs): while
// one CTA waits at __syncthreads/cp.async, the other three feed the tensor
// pipe.  2-stage cp.async double buffer; raw fp32 in smem, cvt.rna on
// fragment load (exact R9 numerics).
// grid.z selects among up to 3 (W,bias,C) sets sharing the same A (fused QKV).
#define G_AS_WORDS   (64 * 36)                      // 2304
#define G_BS_WORDS   (32 * 136)                     // 4352
#define G_STAGE      (G_AS_WORDS + G_BS_WORDS)      // 6656 words
#define G_SMEM_BYTES (2 * G_STAGE * 4)              // 53248 B

__global__ void __launch_bounds__(128, 4) gemm_tf32(
    const float* __restrict__ A,
    const float* __restrict__ W0, const float* __restrict__ b0, float* __restrict__ C0,
    const float* __restrict__ W1, const float* __restrict__ b1, float* __restrict__ C1,
    const float* __restrict__ W2, const float* __restrict__ b2, float* __restrict__ C2,
    int M, int N, int K, int act)
{
    const float* W = W0; const float* bias = b0; float* C = C0;
    if (blockIdx.z == 1) { W = W1; bias = b1; C = C1; }
    else if (blockIdx.z == 2) { W = W2; bias = b2; C = C2; }

    extern __shared__ unsigned gsm[];

    const int tid  = threadIdx.x;
    const int brow = blockIdx.y << 6;          // 64-row tile
    const int bcol = blockIdx.x << 7;          // 128-col tile
    const int w    = tid >> 5, lane = tid & 31;
    const int wn   = w << 5;                   // 0,32,64,96
    const int lr   = lane >> 2, lc = lane & 3;

    const int arow = tid >> 1;                 // 0..63
    const int acol = (tid & 1) << 4;           // 0 / 16
    const int brw  = tid >> 2;                 // 0..31
    const int bcl  = (tid & 3) << 5;           // 0,32,64,96

    const float* Abase = A + (size_t)(brow + arow) * K + acol;
    const float* Wbase = W + (size_t)brw * N + bcol + bcl;

    float acc[4][4][4];
    #pragma unroll
    for (int mt = 0; mt < 4; mt++)
        #pragma unroll
        for (int nt = 0; nt < 4; nt++)
            #pragma unroll
            for (int i = 0; i < 4; i++) acc[mt][nt][i] = 0.f;

    // ---- prologue: chunk 0 into stage 0 ----
    {
        unsigned* As = gsm;
        unsigned* Bs = gsm + G_AS_WORDS;
        #pragma unroll
        for (int i = 0; i < 4; i++)
            cpa16(&As[arow * 36 + acol + i * 4], Abase + i * 4);
        #pragma unroll
        for (int i = 0; i < 8; i++)
            cpa16(&Bs[brw * 136 + bcl + i * 4], Wbase + i * 4);
        asm volatile("cp.async.commit_group;\n");
    }

    for (int k0 = 0; k0 < K; k0 += 32) {
        const int cur = (k0 >> 5) & 1;
        if (k0 + 32 < K) {
            unsigned* As = gsm + (cur ^ 1) * G_STAGE;
            unsigned* Bs = As + G_AS_WORDS;
            const float* Ap = Abase + k0 + 32;
            const float* Wp = Wbase + (size_t)(k0 + 32) * N;
            #pragma unroll
            for (int i = 0; i < 4; i++)
                cpa16(&As[arow * 36 + acol + i * 4], Ap + i * 4);
            #pragma unroll
            for (int i = 0; i < 8; i++)
                cpa16(&Bs[brw * 136 + bcl + i * 4], Wp + i * 4);
            asm volatile("cp.async.commit_group;\n");
            asm volatile("cp.async.wait_group 1;\n");
        } else {
            asm volatile("cp.async.wait_group 0;\n");
        }
        __syncthreads();

        const unsigned* As = gsm + cur * G_STAGE;
        const unsigned* Bs = As + G_AS_WORDS;

        #pragma unroll
        for (int ks = 0; ks < 4; ks++) {
            unsigned a[4][4], bfr[4][2];
            #pragma unroll
            for (int mt = 0; mt < 4; mt++) {
                int r = (mt << 4) + lr;
                int c = (ks << 3) + lc;
                a[mt][0] = raw2tf32(As[r * 36 + c]);
                a[mt][1] = raw2tf32(As[(r + 8) * 36 + c]);
                a[mt][2] = raw2tf32(As[r * 36 + c + 4]);
                a[mt][3] = raw2tf32(As[(r + 8) * 36 + c + 4]);
            }
            #pragma unroll
            for (int nt = 0; nt < 4; nt++) {
                int kk = (ks << 3) + lc;
                int c  = wn + (nt << 3) + lr;
                bfr[nt][0] = raw2tf32(Bs[kk * 136 + c]);
                bfr[nt][1] = raw2tf32(Bs[(kk + 4) * 136 + c]);
            }
            #pragma unroll
            for (int mt = 0; mt < 4; mt++)
                #pragma unroll
                for (int nt = 0; nt < 4; nt++)
                    mma8(acc[mt][nt], a[mt], bfr[nt]);
        }
        __syncthreads();
    }

    #pragma unroll
    for (int mt = 0; mt < 4; mt++) {
        #pragma unroll
        for (int nt = 0; nt < 4; nt++) {
            int r0 = brow + (mt << 4) + lr;
            int c0 = bcol + wn + (nt << 3) + (lc << 1);
            float bx = bias[c0], by = bias[c0 + 1];
            float v0 = acc[mt][nt][0] + bx, v1 = acc[mt][nt][1] + by;
            float v2 = acc[mt][nt][2] + bx, v3 = acc[mt][nt][3] + by;
            if (act == 1) {
                v0 = 0.5f * v0 * (1.f + erff(v0 * 0.70710678f));
                v1 = 0.5f * v1 * (1.f + erff(v1 * 0.70710678f));
                v2 = 0.5f * v2 * (1.f + erff(v2 * 0.70710678f));
                v3 = 0.5f * v3 * (1.f + erff(v3 * 0.70710678f));
            }
            float2 lo = {v0, v1}, hi = {v2, v3};
            *(float2*)(C + (size_t)r0 * N + c0)       = lo;
            *(float2*)(C + (size_t)(r0 + 8) * N + c0) = hi;
        }
    }
}

// ---------------- fused flash attention ------------------------------------
// O = softmax(scale * Q @ K^T [+causal mask]) @ V, one kernel, no gmem S.
// Block: 128 threads (4 warps), Q tile = 64 rows, KV tile = 64 per iter.
// Warp w owns rows [w*16, w*16+16) -> online-softmax stats are warp-local
// (quad shuffles only). P staged through warp-private smem for the 2nd mma.
// smem words:  Qs [64][68] | Ks [64][68] | Vs [64][72] | Ps [64][68]
#define FA_SMEM_WORDS (4352 + 4352 + 4608 + 4352)
#define FA_SMEM_BYTES (FA_SMEM_WORDS * 4)

__global__ void __launch_bounds__(128) flash_attn(
    const float* __restrict__ Q, const float* __restrict__ Km,
    const float* __restrict__ V, float* __restrict__ O,
    int Lq, int Lk, int causal, float scale)
{
    extern __shared__ unsigned sm[];
    unsigned* Qs = sm;
    unsigned* Ks = sm + 4352;
    unsigned* Vs = sm + 8704;
    unsigned* Ps = sm + 13312;

    const int bh = blockIdx.y, b = bh >> 4, h = bh & 15;
    const int i0 = (gridDim.x - 1 - blockIdx.x) << 6;   // heavy tiles first
    const int tid = threadIdx.x;
    const int w = tid >> 5, lane = tid & 31;
    const int lr = lane >> 2, lc = lane & 3;

    // ---- load Q tile once, scale folded in ----
    for (int idx = tid; idx < 1024; idx += 128) {
        int r = idx >> 4, c = (idx & 15) << 2;
        float4 v = *(const float4*)(Q + (size_t)(b * Lq + i0 + r) * DD + h * DKK + c);
        unsigned* d = &Qs[r * 68 + c];
        d[0] = f2tf32(v.x * scale); d[1] = f2tf32(v.y * scale);
        d[2] = f2tf32(v.z * scale); d[3] = f2tf32(v.w * scale);
    }

    float o[8][4];
    #pragma unroll
    for (int nt = 0; nt < 8; nt++)
        #pragma unroll
        for (int i = 0; i < 4; i++) o[nt][i] = 0.f;
    float m0 = -1e30f, m1 = -1e30f, l0 = 0.f, l1 = 0.f;

    const int r = (w << 4) + lr;            // warp-local A-frag row
    const int jend = causal ? (i0 + 64) : Lk;

    for (int j0 = 0; j0 < jend; j0 += 64) {
        __syncthreads();                     // prev iter done before overwrite
        for (int idx = tid; idx < 1024; idx += 128) {
            int rr = idx >> 4, c = (idx & 15) << 2;
            float4 kv = *(const float4*)(Km + (size_t)(b * Lk + j0 + rr) * DD + h * DKK + c);
            unsigned* kd = &Ks[rr * 68 + c];
            kd[0] = f2tf32(kv.x); kd[1] = f2tf32(kv.y);
            kd[2] = f2tf32(kv.z); kd[3] = f2tf32(kv.w);
            float4 vv = *(const float4*)(V + (size_t)(b * Lk + j0 + rr) * DD + h * DKK + c);
            unsigned* vd = &Vs[rr * 72 + c];
            vd[0] = f2tf32(vv.x); vd[1] = f2tf32(vv.y);
            vd[2] = f2tf32(vv.z); vd[3] = f2tf32(vv.w);
        }
        __syncthreads();

        // ---- S = Qs @ Ks^T ----
        float s[8][4];
        #pragma unroll
        for (int nt = 0; nt < 8; nt++)
            #pragma unroll
            for (int i = 0; i < 4; i++) s[nt][i] = 0.f;

        #pragma unroll
        for (int ks = 0; ks < 8; ks++) {
            unsigned a[4];
            int c = (ks << 3) + lc;
            a[0] = Qs[r * 68 + c];
            a[1] = Qs[(r + 8) * 68 + c];
            a[2] = Qs[r * 68 + c + 4];
            a[3] = Qs[(r + 8) * 68 + c + 4];
            #pragma unroll
            for (int nt = 0; nt < 8; nt++) {
                unsigned bb[2];
                int n = (nt << 3) + lr;
                bb[0] = Ks[n * 68 + c];
                bb[1] = Ks[n * 68 + c + 4];
                mma8(s[nt], a, bb);
            }
        }

        // ---- causal mask (diagonal tile only) ----
        if (causal && j0 + 64 > i0) {
            int ig = i0 + r;
            #pragma unroll
            for (int nt = 0; nt < 8; nt++) {
                int jg = j0 + (nt << 3) + (lc << 1);
                if (jg     > ig)     s[nt][0] = -1e30f;
                if (jg + 1 > ig)     s[nt][1] = -1e30f;
                if (jg     > ig + 8) s[nt][2] = -1e30f;
                if (jg + 1 > ig + 8) s[nt][3] = -1e30f;
            }
        }

        // ---- online softmax (rows lr / lr+8 of this warp strip) ----
        float mx0 = -1e30f, mx1 = -1e30f;
        #pragma unroll
        for (int nt = 0; nt < 8; nt++) {
            mx0 = fmaxf(mx0, fmaxf(s[nt][0], s[nt][1]));
            mx1 = fmaxf(mx1, fmaxf(s[nt][2], s[nt][3]));
        }
        mx0 = fmaxf(mx0, __shfl_xor_sync(0xffffffffu, mx0, 1));
        mx0 = fmaxf(mx0, __shfl_xor_sync(0xffffffffu, mx0, 2));
        mx1 = fmaxf(mx1, __shfl_xor_sync(0xffffffffu, mx1, 1));
        mx1 = fmaxf(mx1, __shfl_xor_sync(0xffffffffu, mx1, 2));

        float mn0 = fmaxf(m0, mx0), mn1 = fmaxf(m1, mx1);
        float al0 = __expf(m0 - mn0), al1 = __expf(m1 - mn1);
        m0 = mn0; m1 = mn1;

        float sum0 = 0.f, sum1 = 0.f;
        #pragma unroll
        for (int nt = 0; nt < 8; nt++) {
            float p0 = __expf(s[nt][0] - mn0), p1 = __expf(s[nt][1] - mn0);
            float p2 = __expf(s[nt][2] - mn1), p3 = __expf(s[nt][3] - mn1);
            sum0 += p0 + p1; sum1 += p2 + p3;
            int c = (nt << 3) + (lc << 1);
            Ps[r * 68 + c]           = f2tf32(p0);
            Ps[r * 68 + c + 1]       = f2tf32(p1);
            Ps[(r + 8) * 68 + c]     = f2tf32(p2);
            Ps[(r + 8) * 68 + c + 1] = f2tf32(p3);
            o[nt][0] *= al0; o[nt][1] *= al0;
            o[nt][2] *= al1; o[nt][3] *= al1;
        }
        sum0 += __shfl_xor_sync(0xffffffffu, sum0, 1);
        sum0 += __shfl_xor_sync(0xffffffffu, sum0, 2);
        sum1 += __shfl_xor_sync(0xffffffffu, sum1, 1);
        sum1 += __shfl_xor_sync(0xffffffffu, sum1, 2);
        l0 = l0 * al0 + sum0;
        l1 = l1 * al1 + sum1;
        __syncwarp();                        // Ps visible within warp

        // ---- O += P @ V ----
        #pragma unroll
        for (int ks = 0; ks < 8; ks++) {
            unsigned a[4];
            int c = (ks << 3) + lc;          // shared k index
            a[0] = Ps[r * 68 + c];
            a[1] = Ps[(r + 8) * 68 + c];
            a[2] = Ps[r * 68 + c + 4];
            a[3] = Ps[(r + 8) * 68 + c + 4];
            #pragma unroll
            for (int nt = 0; nt < 8; nt++) {
                unsigned bb[2];
                int n = (nt << 3) + lr;
                bb[0] = Vs[c * 72 + n];
                bb[1] = Vs[(c + 4) * 72 + n];
                mma8(o[nt], a, bb);
            }
        }
    }

    // ---- normalize + store ----
    const float inv0 = 1.f / l0, inv1 = 1.f / l1;
    const int ig = b * Lq + i0 + r;
    #pragma unroll
    for (int nt = 0; nt < 8; nt++) {
        int c = h * DKK + (nt << 3) + (lc << 1);
        float2 lo = {o[nt][0] * inv0, o[nt][1] * inv0};
        float2 hi = {o[nt][2] * inv1, o[nt][3] * inv1};
        *(float2*)(O + (size_t)ig * DD + c)       = lo;
        *(float2*)(O + (size_t)(ig + 8) * DD + c) = hi;
    }
}

// -------------------- out = LayerNorm(a + r) * g + beta ------------------
__global__ void __launch_bounds__(256) add_ln(
    const float* __restrict__ a, const float* __restrict__ r,
    const float* __restrict__ g, const float* __restrict__ beta,
    float* __restrict__ out)
{
    __shared__ float rs[256], rss[256];
    const size_t row = blockIdx.x;
    const int tid = threadIdx.x;
    const int c = tid << 2;
    float4 av = *(const float4*)(a + row * DD + c);
    float4 rv = *(const float4*)(r + row * DD + c);
    float x0 = av.x + rv.x, x1 = av.y + rv.y, x2 = av.z + rv.z, x3 = av.w + rv.w;
    rs[tid]  = x0 + x1 + x2 + x3;
    rss[tid] = x0 * x0 + x1 * x1 + x2 * x2 + x3 * x3;
    __syncthreads();
    for (int s = 128; s > 0; s >>= 1) {
        if (tid < s) { rs[tid] += rs[tid + s]; rss[tid] += rss[tid + s]; }
        __syncthreads();
    }
    const float mu  = rs[0] * (1.f / DD);
    const float var = rss[0] * (1.f / DD) - mu * mu;
    const float inv = rsqrtf(var + 1e-5f);
    float4 gv = *(const float4*)(g + c);
    float4 bv = *(const float4*)(beta + c);
    float4 o;
    o.x = (x0 - mu) * inv * gv.x + bv.x;
    o.y = (x1 - mu) * inv * gv.y + bv.y;
    o.z = (x2 - mu) * inv * gv.z + bv.z;
    o.w = (x3 - mu) * inv * gv.w + bv.w;
    *(float4*)(out + row * DD + c) = o;
}

// ---------------------------------------------------------------------------
extern "C" void kernel_launch(void* const* d_in, const int* in_sizes, int n_in,
                              void* d_out, int out_size)
{
    const float* x        = (const float*)d_in[0];
    const float* enc      = (const float*)d_in[1];
    const float* self_wq = (const float*)d_in[4],  *self_bq = (const float*)d_in[5];
    const float* self_wk = (const float*)d_in[6],  *self_bk = (const float*)d_in[7];
    const float* self_wv = (const float*)d_in[8],  *self_bv = (const float*)d_in[9];
    const float* self_wo = (const float*)d_in[10], *self_bo = (const float*)d_in[11];
    const float* cross_wq = (const float*)d_in[12], *cross_bq = (const float*)d_in[13];
    const float* cross_wk = (const float*)d_in[14], *cross_bk = (const float*)d_in[15];
    const float* cross_wv = (const float*)d_in[16], *cross_bv = (const float*)d_in[17];
    const float* cross_wo = (const float*)d_in[18], *cross_bo = (const float*)d_in[19];
    const float* ff_w1 = (const float*)d_in[20], *ff_b1 = (const float*)d_in[21];
    const float* ff_w2 = (const float*)d_in[22], *ff_b2 = (const float*)d_in[23];
    const float* n1_g = (const float*)d_in[24], *n1_b = (const float*)d_in[25];
    const float* n2_g = (const float*)d_in[26], *n2_b = (const float*)d_in[27];
    const float* n3_g = (const float*)d_in[28], *n3_b = (const float*)d_in[29];
    float* out = (float*)d_out;

    float *q, *k, *v, *attn, *tmp, *x1, *x2, *ff;
    cudaGetSymbolAddress((void**)&q,    g_q);
    cudaGetSymbolAddress((void**)&k,    g_k);
    cudaGetSymbolAddress((void**)&v,    g_v);
    cudaGetSymbolAddress((void**)&attn, g_attn);
    cudaGetSymbolAddress((void**)&tmp,  g_tmp);
    cudaGetSymbolAddress((void**)&x1,   g_x1);
    cudaGetSymbolAddress((void**)&x2,   g_x2);
    cudaGetSymbolAddress((void**)&ff,   g_ff);

    cudaFuncSetAttribute(flash_attn,
                         cudaFuncAttributeMaxDynamicSharedMemorySize, FA_SMEM_BYTES);
    cudaFuncSetAttribute(gemm_tf32,
                         cudaFuncAttributeMaxDynamicSharedMemorySize, G_SMEM_BYTES);

    const dim3 gQKV(DD / 128, MR / 64, 3);
    const dim3 gKV (DD / 128, MR / 64, 2);
    const dim3 gP  (DD / 128, MR / 64, 1);
    const dim3 gFF1(DFFF / 128, MR / 64, 1);
    const dim3 gFA (LTT / 64, BH);
    const float scale = 0.125f;              // 1/sqrt(64)

    // ---- self-attention (causal) ----
    gemm_tf32<<<gQKV, 128, G_SMEM_BYTES>>>(x, self_wq, self_bq, q, self_wk, self_bk, k,
                             self_wv, self_bv, v, MR, DD, DD, 0);
    flash_attn<<<gFA, 128, FA_SMEM_BYTES>>>(q, k, v, attn, LTT, LTT, 1, scale);
    gemm_tf32<<<gP, 128, G_SMEM_BYTES>>>(attn, self_wo, self_bo, tmp,
                           self_wo, self_bo, tmp, self_wo, self_bo, tmp, MR, DD, DD, 0);
    add_ln<<<MR, 256>>>(x, tmp, n1_g, n1_b, x1);

    // ---- cross-attention (no mask) ----
    gemm_tf32<<<gP, 128, G_SMEM_BYTES>>>(x1, cross_wq, cross_bq, q,
                           cross_wq, cross_bq, q, cross_wq, cross_bq, q, MR, DD, DD, 0);
    gemm_tf32<<<gKV, 128, G_SMEM_BYTES>>>(enc, cross_wk, cross_bk, k, cross_wv, cross_bv, v,
                            cross_wv, cross_bv, v, MR, DD, DD, 0);
    flash_attn<<<gFA, 128, FA_SMEM_BYTES>>>(q, k, v, attn, LTT, LSS, 0, scale);
    gemm_tf32<<<gP, 128, G_SMEM_BYTES>>>(attn, cross_wo, cross_bo, tmp,
                           cross_wo, cross_bo, tmp, cross_wo, cross_bo, tmp, MR, DD, DD, 0);
    add_ln<<<MR, 256>>>(x1, tmp, n2_g, n2_b, x2);

    // ---- feed-forward ----
    gemm_tf32<<<gFF1, 128, G_SMEM_BYTES>>>(x2, ff_w1, ff_b1, ff,
                             ff_w1, ff_b1, ff, ff_w1, ff_b1, ff, MR, DFFF, DD, 1);
    gemm_tf32<<<gP, 128, G_SMEM_BYTES>>>(ff, ff_w2, ff_b2, tmp,
                           ff_w2, ff_b2, tmp, ff_w2, ff_b2, tmp, MR, DD, DFFF, 0);
    add_ln<<<MR, 256>>>(x2, tmp, n3_g, n3_b, out);
}

// round 17
// speedup vs baseline: 1.7738x; 1.7738x over previous
#include <cuda_runtime.h>
#include <cuda_fp16.h>
#include <math.h>
#include <stdint.h>

// Problem dims
#define BB   2
#define LTT  2048
#define LSS  2048
#define DD   1024
#define HH   16
#define DKK  64
#define DFFF 4096
#define MR   (BB*LTT)   // 4096 rows
#define BH   (BB*HH)    // 32
#define M1   (1u << 20)

// ---------------- scratch (__device__ globals, no allocs) ----------------
__device__ float  g_q   [(size_t)MR*DD];
__device__ float  g_k   [(size_t)MR*DD];
__device__ float  g_v   [(size_t)MR*DD];
__device__ float  g_tmp [(size_t)MR*DD];
__device__ float  g_x1  [(size_t)MR*DD];
__device__ float  g_x2  [(size_t)MR*DD];
__device__ __half g_xh  [(size_t)MR*DD];
__device__ __half g_ench[(size_t)MR*DD];
__device__ __half g_atth[(size_t)MR*DD];
__device__ __half g_x1h [(size_t)MR*DD];
__device__ __half g_x2h [(size_t)MR*DD];
__device__ __half g_ffh [(size_t)MR*DFFF];
__device__ __half g_wt  [(size_t)16*M1];   // transposed fp16 weights [N][K]

// ------------------------- helpers -----------------------------------
__device__ __forceinline__ unsigned f2tf32(float x) {
    unsigned y;
    asm("cvt.rna.tf32.f32 %0, %1;" : "=r"(y) : "f"(x));
    return y;
}

// tf32 mma for flash attention (proven path)
__device__ __forceinline__ void mma8(float* d, const unsigned* a, const unsigned* b) {
    asm volatile(
        "mma.sync.aligned.m16n8k8.row.col.f32.tf32.tf32.f32 "
        "{%0,%1,%2,%3},{%4,%5,%6,%7},{%8,%9},{%0,%1,%2,%3};\n"
        : "+f"(d[0]), "+f"(d[1]), "+f"(d[2]), "+f"(d[3])
        : "r"(a[0]), "r"(a[1]), "r"(a[2]), "r"(a[3]), "r"(b[0]), "r"(b[1]));
}

// fp16 mma m16n8k16, fp32 accumulate
__device__ __forceinline__ void mma16h(float* d, const unsigned* a, const unsigned* b) {
    asm volatile(
        "mma.sync.aligned.m16n8k16.row.col.f32.f16.f16.f32 "
        "{%0,%1,%2,%3},{%4,%5,%6,%7},{%8,%9},{%0,%1,%2,%3};\n"
        : "+f"(d[0]), "+f"(d[1]), "+f"(d[2]), "+f"(d[3])
        : "r"(a[0]), "r"(a[1]), "r"(a[2]), "r"(a[3]), "r"(b[0]), "r"(b[1]));
}

__device__ __forceinline__ void cpa16(unsigned* dst, const void* src) {
    unsigned d = (unsigned)__cvta_generic_to_shared(dst);
    asm volatile("cp.async.cg.shared.global [%0], [%1], 16;\n" :: "r"(d), "l"(src));
}

__device__ __forceinline__ unsigned packh2(float a, float b) {
    __half2 h = __float22half2_rn(make_float2(a, b));
    return *(unsigned*)&h;
}

// ----------------- prologue: fp32 -> fp16 straight convert ---------------
__global__ void __launch_bounds__(256) cvt_f16(
    const float* __restrict__ S, __half* __restrict__ D, int n)
{
    int i = (blockIdx.x * 256 + threadIdx.x) * 4;
    if (i >= n) return;
    float4 v = *(const float4*)(S + i);
    unsigned u0 = packh2(v.x, v.y);
    unsigned u1 = packh2(v.z, v.w);
    *(uint2*)((unsigned*)D + (i >> 1)) = make_uint2(u0, u1);
}

// ----------- prologue: W [K,N] fp32 -> WT [N,K] fp16 (tiled) --------------
__global__ void __launch_bounds__(256) tr_cvt(
    const float* __restrict__ S, __half* __restrict__ D, int K, int N)
{
    __shared__ float t[32][33];
    const int k0 = blockIdx.x << 5, n0 = blockIdx.y << 5;
    const int tx = threadIdx.x & 31, ty = threadIdx.x >> 5;   // 32 x 8
    #pragma unroll
    for (int i = 0; i < 4; i++)
        t[ty + i * 8][tx] = S[(size_t)(k0 + ty + i * 8) * N + n0 + tx];
    __syncthreads();
    #pragma unroll
    for (int i = 0; i < 4; i++)
        D[(size_t)(n0 + ty + i * 8) * K + k0 + tx] = __float2half_rn(t[tx][ty + i * 8]);
}

// ------------- fp16 GEMM: C = A[M,K] @ W[K,N] + bias (+gelu) --------------
// A fp16 [M,K], WT fp16 [N,K].  128x128 tile, BK=64, 256 threads (8 warps
// 2x4, warp tile 64x32), 2-stage cp.async double buffer.
// smem rows: 64 halfs = 32 words, padded to 36 -> conflict-free fragments.
// mode 0: fp32 out.  mode 1: gelu + fp16-pair out.
// grid.z selects among up to 3 (W,bias,C) sets sharing the same A.
#define GH_ROWW   36
#define GH_STAGE  (2 * 128 * GH_ROWW)               // A + B, words
#define GH_SMEM   (2 * GH_STAGE * 4)                // 73728 B

__global__ void __launch_bounds__(256, 2) gemm_f16(
    const __half* __restrict__ A,
    const __half* __restrict__ W0, const float* __restrict__ b0, void* C0,
    const __half* __restrict__ W1, const float* __restrict__ b1, void* C1,
    const __half* __restrict__ W2, const float* __restrict__ b2, void* C2,
    int M, int N, int K, int mode)
{
    const __half* W = W0; const float* bias = b0; void* C = C0;
    if (blockIdx.z == 1) { W = W1; bias = b1; C = C1; }
    else if (blockIdx.z == 2) { W = W2; bias = b2; C = C2; }

    extern __shared__ unsigned gsm[];

    const int tid  = threadIdx.x;
    const int brow = blockIdx.y << 7;
    const int bcol = blockIdx.x << 7;
    const int w    = tid >> 5, lane = tid & 31;
    const int wm   = (w & 1) << 6;
    const int wn   = (w >> 1) << 5;
    const int lr   = lane >> 2, lc = lane & 3;

    const int arow = tid >> 1;                 // 0..127
    const int half = tid & 1;                  // which 64B half of the row

    const char* Abase = (const char*)(A + (size_t)(brow + arow) * K) + half * 64;
    const char* Bbase = (const char*)(W + (size_t)(bcol + arow) * K) + half * 64;
    const int dstw = arow * GH_ROWW + half * 16;

    float acc[4][4][4];
    #pragma unroll
    for (int mt = 0; mt < 4; mt++)
        #pragma unroll
        for (int nt = 0; nt < 4; nt++)
            #pragma unroll
            for (int i = 0; i < 4; i++) acc[mt][nt][i] = 0.f;

    // ---- prologue: chunk 0 into stage 0 ----
    {
        unsigned* As = gsm;
        unsigned* Bs = gsm + 128 * GH_ROWW;
        #pragma unroll
        for (int i = 0; i < 4; i++) {
            cpa16(&As[dstw + i * 4], Abase + i * 16);
            cpa16(&Bs[dstw + i * 4], Bbase + i * 16);
        }
        asm volatile("cp.async.commit_group;\n");
    }

    const int nch = K >> 6;
    for (int c = 0; c < nch; c++) {
        const int cur = c & 1;
        if (c + 1 < nch) {
            unsigned* As = gsm + (cur ^ 1) * GH_STAGE;
            unsigned* Bs = As + 128 * GH_ROWW;
            const char* Ap = Abase + (size_t)(c + 1) * 128;   // 64 halfs = 128 B
            const char* Bp = Bbase + (size_t)(c + 1) * 128;
            #pragma unroll
            for (int i = 0; i < 4; i++) {
                cpa16(&As[dstw + i * 4], Ap + i * 16);
                cpa16(&Bs[dstw + i * 4], Bp + i * 16);
            }
            asm volatile("cp.async.commit_group;\n");
            asm volatile("cp.async.wait_group 1;\n");
        } else {
            asm volatile("cp.async.wait_group 0;\n");
        }
        __syncthreads();

        const unsigned* As = gsm + cur * GH_STAGE;
        const unsigned* Bs = As + 128 * GH_ROWW;

        #pragma unroll
        for (int ks = 0; ks < 4; ks++) {
            unsigned a[4][4], bfr[4][2];
            const int cb = (ks << 3) + lc;
            #pragma unroll
            for (int mt = 0; mt < 4; mt++) {
                int r = wm + (mt << 4) + lr;
                a[mt][0] = As[r * GH_ROWW + cb];
                a[mt][1] = As[(r + 8) * GH_ROWW + cb];
                a[mt][2] = As[r * GH_ROWW + cb + 4];
                a[mt][3] = As[(r + 8) * GH_ROWW + cb + 4];
            }
            #pragma unroll
            for (int nt = 0; nt < 4; nt++) {
                int n = wn + (nt << 3) + lr;
                bfr[nt][0] = Bs[n * GH_ROWW + cb];
                bfr[nt][1] = Bs[n * GH_ROWW + cb + 4];
            }
            #pragma unroll
            for (int mt = 0; mt < 4; mt++)
                #pragma unroll
                for (int nt = 0; nt < 4; nt++)
                    mma16h(acc[mt][nt], a[mt], bfr[nt]);
        }
        __syncthreads();
    }

    #pragma unroll
    for (int mt = 0; mt < 4; mt++) {
        #pragma unroll
        for (int nt = 0; nt < 4; nt++) {
            int r0 = brow + wm + (mt << 4) + lr;
            int c0 = bcol + wn + (nt << 3) + (lc << 1);
            float bx = bias[c0], by = bias[c0 + 1];
            float v0 = acc[mt][nt][0] + bx, v1 = acc[mt][nt][1] + by;
            float v2 = acc[mt][nt][2] + bx, v3 = acc[mt][nt][3] + by;
            if (mode == 1) {
                v0 = 0.5f * v0 * (1.f + erff(v0 * 0.70710678f));
                v1 = 0.5f * v1 * (1.f + erff(v1 * 0.70710678f));
                v2 = 0.5f * v2 * (1.f + erff(v2 * 0.70710678f));
                v3 = 0.5f * v3 * (1.f + erff(v3 * 0.70710678f));
                unsigned* Ch = (unsigned*)C;
                Ch[((size_t)r0 * N + c0) >> 1]       = packh2(v0, v1);
                Ch[((size_t)(r0 + 8) * N + c0) >> 1] = packh2(v2, v3);
            } else {
                float* Cf = (float*)C;
                float2 lo = {v0, v1}, hi = {v2, v3};
                *(float2*)(Cf + (size_t)r0 * N + c0)       = lo;
                *(float2*)(Cf + (size_t)(r0 + 8) * N + c0) = hi;
            }
        }
    }
}

// ---------------- fused flash attention (tf32, fp16 output) ----------------
// smem words:  Qs [64][68] | Ks [64][68] | Vs [64][72] | Ps [64][68]
#define FA_SMEM_WORDS (4352 + 4352 + 4608 + 4352)
#define FA_SMEM_BYTES (FA_SMEM_WORDS * 4)

__global__ void __launch_bounds__(128) flash_attn(
    const float* __restrict__ Q, const float* __restrict__ Km,
    const float* __restrict__ V, unsigned* __restrict__ Oh,
    int Lq, int Lk, int causal, float scale)
{
    extern __shared__ unsigned sm[];
    unsigned* Qs = sm;
    unsigned* Ks = sm + 4352;
    unsigned* Vs = sm + 8704;
    unsigned* Ps = sm + 13312;

    const int bh = blockIdx.y, b = bh >> 4, h = bh & 15;
    const int i0 = (gridDim.x - 1 - blockIdx.x) << 6;
    const int tid = threadIdx.x;
    const int w = tid >> 5, lane = tid & 31;
    const int lr = lane >> 2, lc = lane & 3;

    for (int idx = tid; idx < 1024; idx += 128) {
        int r = idx >> 4, c = (idx & 15) << 2;
        float4 v = *(const float4*)(Q + (size_t)(b * Lq + i0 + r) * DD + h * DKK + c);
        unsigned* d = &Qs[r * 68 + c];
        d[0] = f2tf32(v.x * scale); d[1] = f2tf32(v.y * scale);
        d[2] = f2tf32(v.z * scale); d[3] = f2tf32(v.w * scale);
    }

    float o[8][4];
    #pragma unroll
    for (int nt = 0; nt < 8; nt++)
        #pragma unroll
        for (int i = 0; i < 4; i++) o[nt][i] = 0.f;
    float m0 = -1e30f, m1 = -1e30f, l0 = 0.f, l1 = 0.f;

    const int r = (w << 4) + lr;
    const int jend = causal ? (i0 + 64) : Lk;

    for (int j0 = 0; j0 < jend; j0 += 64) {
        __syncthreads();
        for (int idx = tid; idx < 1024; idx += 128) {
            int rr = idx >> 4, c = (idx & 15) << 2;
            float4 kv = *(const float4*)(Km + (size_t)(b * Lk + j0 + rr) * DD + h * DKK + c);
            unsigned* kd = &Ks[rr * 68 + c];
            kd[0] = f2tf32(kv.x); kd[1] = f2tf32(kv.y);
            kd[2] = f2tf32(kv.z); kd[3] = f2tf32(kv.w);
            float4 vv = *(const float4*)(V + (size_t)(b * Lk + j0 + rr) * DD + h * DKK + c);
            unsigned* vd = &Vs[rr * 72 + c];
            vd[0] = f2tf32(vv.x); vd[1] = f2tf32(vv.y);
            vd[2] = f2tf32(vv.z); vd[3] = f2tf32(vv.w);
        }
        __syncthreads();

        float s[8][4];
        #pragma unroll
        for (int nt = 0; nt < 8; nt++)
            #pragma unroll
            for (int i = 0; i < 4; i++) s[nt][i] = 0.f;

        #pragma unroll
        for (int ks = 0; ks < 8; ks++) {
            unsigned a[4];
            int c = (ks << 3) + lc;
            a[0] = Qs[r * 68 + c];
            a[1] = Qs[(r + 8) * 68 + c];
            a[2] = Qs[r * 68 + c + 4];
            a[3] = Qs[(r + 8) * 68 + c + 4];
            #pragma unroll
            for (int nt = 0; nt < 8; nt++) {
                unsigned bb[2];
                int n = (nt << 3) + lr;
                bb[0] = Ks[n * 68 + c];
                bb[1] = Ks[n * 68 + c + 4];
                mma8(s[nt], a, bb);
            }
        }

        if (causal && j0 + 64 > i0) {
            int ig = i0 + r;
            #pragma unroll
            for (int nt = 0; nt < 8; nt++) {
                int jg = j0 + (nt << 3) + (lc << 1);
                if (jg     > ig)     s[nt][0] = -1e30f;
                if (jg + 1 > ig)     s[nt][1] = -1e30f;
                if (jg     > ig + 8) s[nt][2] = -1e30f;
                if (jg + 1 > ig + 8) s[nt][3] = -1e30f;
            }
        }

        float mx0 = -1e30f, mx1 = -1e30f;
        #pragma unroll
        for (int nt = 0; nt < 8; nt++) {
            mx0 = fmaxf(mx0, fmaxf(s[nt][0], s[nt][1]));
            mx1 = fmaxf(mx1, fmaxf(s[nt][2], s[nt][3]));
        }
        mx0 = fmaxf(mx0, __shfl_xor_sync(0xffffffffu, mx0, 1));
        mx0 = fmaxf(mx0, __shfl_xor_sync(0xffffffffu, mx0, 2));
        mx1 = fmaxf(mx1, __shfl_xor_sync(0xffffffffu, mx1, 1));
        mx1 = fmaxf(mx1, __shfl_xor_sync(0xffffffffu, mx1, 2));

        float mn0 = fmaxf(m0, mx0), mn1 = fmaxf(m1, mx1);
        float al0 = __expf(m0 - mn0), al1 = __expf(m1 - mn1);
        m0 = mn0; m1 = mn1;

        float sum0 = 0.f, sum1 = 0.f;
        #pragma unroll
        for (int nt = 0; nt < 8; nt++) {
            float p0 = __expf(s[nt][0] - mn0), p1 = __expf(s[nt][1] - mn0);
            float p2 = __expf(s[nt][2] - mn1), p3 = __expf(s[nt][3] - mn1);
            sum0 += p0 + p1; sum1 += p2 + p3;
            int c = (nt << 3) + (lc << 1);
            Ps[r * 68 + c]           = f2tf32(p0);
            Ps[r * 68 + c + 1]       = f2tf32(p1);
            Ps[(r + 8) * 68 + c]     = f2tf32(p2);
            Ps[(r + 8) * 68 + c + 1] = f2tf32(p3);
            o[nt][0] *= al0; o[nt][1] *= al0;
            o[nt][2] *= al1; o[nt][3] *= al1;
        }
        sum0 += __shfl_xor_sync(0xffffffffu, sum0, 1);
        sum0 += __shfl_xor_sync(0xffffffffu, sum0, 2);
        sum1 += __shfl_xor_sync(0xffffffffu, sum1, 1);
        sum1 += __shfl_xor_sync(0xffffffffu, sum1, 2);
        l0 = l0 * al0 + sum0;
        l1 = l1 * al1 + sum1;
        __syncwarp();

        #pragma unroll
        for (int ks = 0; ks < 8; ks++) {
            unsigned a[4];
            int c = (ks << 3) + lc;
            a[0] = Ps[r * 68 + c];
            a[1] = Ps[(r + 8) * 68 + c];
            a[2] = Ps[r * 68 + c + 4];
            a[3] = Ps[(r + 8) * 68 + c + 4];
            #pragma unroll
            for (int nt = 0; nt < 8; nt++) {
                unsigned bb[2];
                int n = (nt << 3) + lr;
                bb[0] = Vs[c * 72 + n];
                bb[1] = Vs[(c + 4) * 72 + n];
                mma8(o[nt], a, bb);
            }
        }
    }

    // ---- normalize + fp16 store (consumer is the fp16 O-projection) ----
    const float inv0 = 1.f / l0, inv1 = 1.f / l1;
    const int ig = b * Lq + i0 + r;
    #pragma unroll
    for (int nt = 0; nt < 8; nt++) {
        int c = h * DKK + (nt << 3) + (lc << 1);
        Oh[((size_t)ig * DD + c) >> 1]       = packh2(o[nt][0] * inv0, o[nt][1] * inv0);
        Oh[((size_t)(ig + 8) * DD + c) >> 1] = packh2(o[nt][2] * inv1, o[nt][3] * inv1);
    }
}

// ------- out = LayerNorm(a + r) * g + beta (+ optional fp16 copy) ---------
__global__ void __launch_bounds__(256) add_ln(
    const float* __restrict__ a, const float* __restrict__ r,
    const float* __restrict__ g, const float* __restrict__ beta,
    float* __restrict__ out, unsigned* __restrict__ out_h)
{
    __shared__ float rs[256], rss[256];
    const size_t row = blockIdx.x;
    const int tid = threadIdx.x;
    const int c = tid << 2;
    float4 av = *(const float4*)(a + row * DD + c);
    float4 rv = *(const float4*)(r + row * DD + c);
    float x0 = av.x + rv.x, x1 = av.y + rv.y, x2 = av.z + rv.z, x3 = av.w + rv.w;
    rs[tid]  = x0 + x1 + x2 + x3;
    rss[tid] = x0 * x0 + x1 * x1 + x2 * x2 + x3 * x3;
    __syncthreads();
    for (int s = 128; s > 0; s >>= 1) {
        if (tid < s) { rs[tid] += rs[tid + s]; rss[tid] += rss[tid + s]; }
        __syncthreads();
    }
    const float mu  = rs[0] * (1.f / DD);
    const float var = rss[0] * (1.f / DD) - mu * mu;
    const float inv = rsqrtf(var + 1e-5f);
    float4 gv = *(const float4*)(g + c);
    float4 bv = *(const float4*)(beta + c);
    float4 o;
    o.x = (x0 - mu) * inv * gv.x + bv.x;
    o.y = (x1 - mu) * inv * gv.y + bv.y;
    o.z = (x2 - mu) * inv * gv.z + bv.z;
    o.w = (x3 - mu) * inv * gv.w + bv.w;
    *(float4*)(out + row * DD + c) = o;
    if (out_h) {
        uint2 u = make_uint2(packh2(o.x, o.y), packh2(o.z, o.w));
        *(uint2*)(out_h + ((row * DD + c) >> 1)) = u;
    }
}

// ---------------------------------------------------------------------------
extern "C" void kernel_launch(void* const* d_in, const int* in_sizes, int n_in,
                              void* d_out, int out_size)
{
    const float* x        = (const float*)d_in[0];
    const float* enc      = (const float*)d_in[1];
    const float* self_wq = (const float*)d_in[4],  *self_bq = (const float*)d_in[5];
    const float* self_wk = (const float*)d_in[6],  *self_bk = (const float*)d_in[7];
    const float* self_wv = (const float*)d_in[8],  *self_bv = (const float*)d_in[9];
    const float* self_wo = (const float*)d_in[10], *self_bo = (const float*)d_in[11];
    const float* cross_wq = (const float*)d_in[12], *cross_bq = (const float*)d_in[13];
    const float* cross_wk = (const float*)d_in[14], *cross_bk = (const float*)d_in[15];
    const float* cross_wv = (const float*)d_in[16], *cross_bv = (const float*)d_in[17];
    const float* cross_wo = (const float*)d_in[18], *cross_bo = (const float*)d_in[19];
    const float* ff_w1 = (const float*)d_in[20], *ff_b1 = (const float*)d_in[21];
    const float* ff_w2 = (const float*)d_in[22], *ff_b2 = (const float*)d_in[23];
    const float* n1_g = (const float*)d_in[24], *n1_b = (const float*)d_in[25];
    const float* n2_g = (const float*)d_in[26], *n2_b = (const float*)d_in[27];
    const float* n3_g = (const float*)d_in[28], *n3_b = (const float*)d_in[29];
    float* out = (float*)d_out;

    float  *q, *k, *v, *tmp, *x1, *x2;
    __half *xh, *ench, *atth, *x1h, *x2h, *ffh, *wt;
    cudaGetSymbolAddress((void**)&q,    g_q);
    cudaGetSymbolAddress((void**)&k,    g_k);
    cudaGetSymbolAddress((void**)&v,    g_v);
    cudaGetSymbolAddress((void**)&tmp,  g_tmp);
    cudaGetSymbolAddress((void**)&x1,   g_x1);
    cudaGetSymbolAddress((void**)&x2,   g_x2);
    cudaGetSymbolAddress((void**)&xh,   g_xh);
    cudaGetSymbolAddress((void**)&ench, g_ench);
    cudaGetSymbolAddress((void**)&atth, g_atth);
    cudaGetSymbolAddress((void**)&x1h,  g_x1h);
    cudaGetSymbolAddress((void**)&x2h,  g_x2h);
    cudaGetSymbolAddress((void**)&ffh,  g_ffh);
    cudaGetSymbolAddress((void**)&wt,   g_wt);

    cudaFuncSetAttribute(flash_attn,
                         cudaFuncAttributeMaxDynamicSharedMemorySize, FA_SMEM_BYTES);
    cudaFuncSetAttribute(gemm_f16,
                         cudaFuncAttributeMaxDynamicSharedMemorySize, GH_SMEM);

    // transposed-weight arena offsets (halfs)
    __half* t_swq = wt;            __half* t_swk = wt + 1*M1;
    __half* t_swv = wt + 2*M1;     __half* t_swo = wt + 3*M1;
    __half* t_cwq = wt + 4*M1;     __half* t_cwk = wt + 5*M1;
    __half* t_cwv = wt + 6*M1;     __half* t_cwo = wt + 7*M1;
    __half* t_ffw1 = wt + 8*M1;    __half* t_ffw2 = wt + 12*M1;

    const dim3 gQKV(DD / 128, MR / 128, 3);
    const dim3 gKV (DD / 128, MR / 128, 2);
    const dim3 gP  (DD / 128, MR / 128, 1);
    const dim3 gFF1(DFFF / 128, MR / 128, 1);
    const dim3 gFA (LTT / 64, BH);
    const dim3 bTR (256);
    const float scale = 0.125f;              // 1/sqrt(64)

    // ---- prologue: convert activations + transpose/convert weights ----
    cvt_f16<<<4096, 256>>>(x,   xh,   MR * DD);
    cvt_f16<<<4096, 256>>>(enc, ench, MR * DD);
    tr_cvt<<<dim3(32, 32),  bTR>>>(self_wq,  t_swq,  DD, DD);
    tr_cvt<<<dim3(32, 32),  bTR>>>(self_wk,  t_swk,  DD, DD);
    tr_cvt<<<dim3(32, 32),  bTR>>>(self_wv,  t_swv,  DD, DD);
    tr_cvt<<<dim3(32, 32),  bTR>>>(self_wo,  t_swo,  DD, DD);
    tr_cvt<<<dim3(32, 32),  bTR>>>(cross_wq, t_cwq,  DD, DD);
    tr_cvt<<<dim3(32, 32),  bTR>>>(cross_wk, t_cwk,  DD, DD);
    tr_cvt<<<dim3(32, 32),  bTR>>>(cross_wv, t_cwv,  DD, DD);
    tr_cvt<<<dim3(32, 32),  bTR>>>(cross_wo, t_cwo,  DD, DD);
    tr_cvt<<<dim3(32, 128), bTR>>>(ff_w1,    t_ffw1, DD, DFFF);
    tr_cvt<<<dim3(128, 32), bTR>>>(ff_w2,    t_ffw2, DFFF, DD);

    // ---- self-attention (causal) ----
    gemm_f16<<<gQKV, 256, GH_SMEM>>>(xh, t_swq, self_bq, q, t_swk, self_bk, k,
                                     t_swv, self_bv, v, MR, DD, DD, 0);
    flash_attn<<<gFA, 128, FA_SMEM_BYTES>>>(q, k, v, (unsigned*)atth, LTT, LTT, 1, scale);
    gemm_f16<<<gP, 256, GH_SMEM>>>(atth, t_swo, self_bo, tmp,
                                   t_swo, self_bo, tmp, t_swo, self_bo, tmp, MR, DD, DD, 0);
    add_ln<<<MR, 256>>>(x, tmp, n1_g, n1_b, x1, (unsigned*)x1h);

    // ---- cross-attention (no mask) ----
    gemm_f16<<<gP, 256, GH_SMEM>>>(x1h, t_cwq, cross_bq, q,
                                   t_cwq, cross_bq, q, t_cwq, cross_bq, q, MR, DD, DD, 0);
    gemm_f16<<<gKV, 256, GH_SMEM>>>(ench, t_cwk, cross_bk, k, t_cwv, cross_bv, v,
                                    t_cwv, cross_bv, v, MR, DD, DD, 0);
    flash_attn<<<gFA, 128, FA_SMEM_BYTES>>>(q, k, v, (unsigned*)atth, LTT, LSS, 0, scale);
    gemm_f16<<<gP, 256, GH_SMEM>>>(atth, t_cwo, cross_bo, tmp,
                                   t_cwo, cross_bo, tmp, t_cwo, cross_bo, tmp, MR, DD, DD, 0);
    add_ln<<<MR, 256>>>(x1, tmp, n2_g, n2_b, x2, (unsigned*)x2h);

    // ---- feed-forward (FF1 writes fp16 directly; FF2 back to fp32) ----
    gemm_f16<<<gFF1, 256, GH_SMEM>>>(x2h, t_ffw1, ff_b1, ffh,
                                     t_ffw1, ff_b1, ffh, t_ffw1, ff_b1, ffh,
                                     MR, DFFF, DD, 1);
    gemm_f16<<<gP, 256, GH_SMEM>>>(ffh, t_ffw2, ff_b2, tmp,
                                   t_ffw2, ff_b2, tmp, t_ffw2, ff_b2, tmp,
                                   MR, DD, DFFF, 0);
    add_ln<<<MR, 256>>>(x2, tmp, n3_g, n3_b, out, (unsigned*)0);
}